// round 1
// baseline (speedup 1.0000x reference)
#include <cuda_runtime.h>
#include <cuda_bf16.h>
#include <cstdint>

// Problem constants (fixed by the reference: N = 1048576, D = 64, exactly N/2 per partition)
constexpr int N_ELEMS   = 1 << 20;
constexpr int THREADS   = 256;
constexpr int EPB       = THREADS * 4;      // 1024 elements per block (int4 per thread)
constexpr int NBLK      = N_ELEMS / EPB;    // 1024 blocks

// Scratch (no device allocation allowed -> __device__ globals)
__device__ int g_blockCounts[NBLK];
__device__ int g_blockOffsets[NBLK];
__device__ int g_dest[N_ELEMS];

// ---------------------------------------------------------------------------
// Kernel 1: per-block count of (partitions == 0)
// ---------------------------------------------------------------------------
__global__ void count_k(const int* __restrict__ part) {
    int base = blockIdx.x * EPB + threadIdx.x * 4;
    int4 p = *reinterpret_cast<const int4*>(part + base);
    int c = (p.x == 0) + (p.y == 0) + (p.z == 0) + (p.w == 0);

    #pragma unroll
    for (int o = 16; o; o >>= 1) c += __shfl_down_sync(0xffffffffu, c, o);

    __shared__ int ws[THREADS / 32];
    if ((threadIdx.x & 31) == 0) ws[threadIdx.x >> 5] = c;
    __syncthreads();
    if (threadIdx.x < THREADS / 32) {
        int v = ws[threadIdx.x];
        #pragma unroll
        for (int o = (THREADS / 32) / 2; o; o >>= 1)
            v += __shfl_down_sync(0xffu, v, o);
        if (threadIdx.x == 0) g_blockCounts[blockIdx.x] = v;
    }
}

// ---------------------------------------------------------------------------
// Kernel 2: exclusive scan of NBLK (=1024) block counts, single block of 1024
// ---------------------------------------------------------------------------
__global__ void scan_k() {
    int t = threadIdx.x;              // 0..1023
    int v = g_blockCounts[t];
    int lane = t & 31, w = t >> 5;    // 32 warps

    // inclusive warp scan
    int s = v;
    #pragma unroll
    for (int o = 1; o < 32; o <<= 1) {
        int n = __shfl_up_sync(0xffffffffu, s, o);
        if (lane >= o) s += n;
    }

    __shared__ int wsum[32];
    if (lane == 31) wsum[w] = s;
    __syncthreads();
    if (w == 0) {
        int x = wsum[lane];
        #pragma unroll
        for (int o = 1; o < 32; o <<= 1) {
            int n = __shfl_up_sync(0xffffffffu, x, o);
            if (lane >= o) x += n;
        }
        wsum[lane] = x;   // inclusive scan of warp sums
    }
    __syncthreads();

    int excl = s - v + (w > 0 ? wsum[w - 1] : 0);
    g_blockOffsets[t] = excl;
}

// ---------------------------------------------------------------------------
// Kernel 3: compute destination row for every element
//   zerosBefore(i) -> dest = p==0 ? index0[zb] : index1[i - zb]
// ---------------------------------------------------------------------------
__global__ void dest_k(const int* __restrict__ part,
                       const int* __restrict__ idx0,
                       const int* __restrict__ idx1) {
    int t = threadIdx.x;
    int base = blockIdx.x * EPB + t * 4;
    int4 p = *reinterpret_cast<const int4*>(part + base);
    int b0 = (p.x == 0), b1 = (p.y == 0), b2 = (p.z == 0), b3 = (p.w == 0);
    int c = b0 + b1 + b2 + b3;

    // block-level inclusive scan of per-thread counts
    int lane = t & 31, w = t >> 5;
    int s = c;
    #pragma unroll
    for (int o = 1; o < 32; o <<= 1) {
        int n = __shfl_up_sync(0xffffffffu, s, o);
        if (lane >= o) s += n;
    }
    __shared__ int wsum[THREADS / 32];
    if (lane == 31) wsum[w] = s;
    __syncthreads();
    if (t < THREADS / 32) {
        int x = wsum[t];
        #pragma unroll
        for (int o = 1; o < THREADS / 32; o <<= 1) {
            int n = __shfl_up_sync(0xffu, x, o);
            if (t >= o) x += n;
        }
        wsum[t] = x;
    }
    __syncthreads();

    int zb = (s - c) + (w > 0 ? wsum[w - 1] : 0) + g_blockOffsets[blockIdx.x];

    int4 d;
    int i = base;
    d.x = b0 ? __ldg(idx0 + zb) : __ldg(idx1 + (i - zb)); zb += b0; i++;
    d.y = b1 ? __ldg(idx0 + zb) : __ldg(idx1 + (i - zb)); zb += b1; i++;
    d.z = b2 ? __ldg(idx0 + zb) : __ldg(idx1 + (i - zb)); zb += b2; i++;
    d.w = b3 ? __ldg(idx0 + zb) : __ldg(idx1 + (i - zb));

    *reinterpret_cast<int4*>(g_dest + base) = d;
}

// ---------------------------------------------------------------------------
// Kernel 4: row scatter. 16 lanes * float4 = one 256B row.
//   Reads fully coalesced; each row's write is a contiguous 256B chunk.
// ---------------------------------------------------------------------------
__global__ void scatter_k(const float4* __restrict__ in, float4* __restrict__ out) {
    unsigned s = blockIdx.x * blockDim.x + threadIdx.x;  // 0 .. N*16-1
    unsigned row  = s >> 4;
    unsigned lane = s & 15;
    int drow = __ldg(g_dest + row);
    out[(size_t)drow * 16 + lane] = in[(size_t)row * 16 + lane];
}

// ---------------------------------------------------------------------------
extern "C" void kernel_launch(void* const* d_in, const int* in_sizes, int n_in,
                              void* d_out, int out_size) {
    const float* data = (const float*)d_in[0];
    const int*   part = (const int*)d_in[1];
    const int*   idx0 = (const int*)d_in[2];
    const int*   idx1 = (const int*)d_in[3];
    float* out = (float*)d_out;

    count_k<<<NBLK, THREADS>>>(part);
    scan_k<<<1, NBLK>>>();
    dest_k<<<NBLK, THREADS>>>(part, idx0, idx1);

    // N rows * 16 float4 slots each
    int total_slots = N_ELEMS * 16;                 // 16M
    int blocks = total_slots / THREADS;             // 65536
    scatter_k<<<blocks, THREADS>>>((const float4*)data, (float4*)out);
}